// round 1
// baseline (speedup 1.0000x reference)
#include <cuda_runtime.h>

// Problem constants (fixed shapes per reference)
#define BATCH       256
#define DIM         256
#define NUM_TRUE    1024
#define NUM_SAMPLED 16384

// GEMM tiling
#define BM 128
#define BN 128
#define BK 8
#define TM 8
#define TN 8
#define NB_N (NUM_SAMPLED / BN)   // 128 n-blocks

// ---------------- device scratch (no allocations allowed) ----------------
__device__ float g_off_sampled[NUM_SAMPLED];          // bias[sampled] - log(ec)
__device__ float g_partial_sampled[NB_N * BATCH];     // [n_block][b]
__device__ float g_true_part[2 * BATCH];              // [chunk][b]

// ---------------- math helpers (mirror reference numerics) ----------------
// LOG_RANGE = log(NUM_CLASSES + 1) = log(100001)
#define LOG_RANGE 11.5129354649202280f

__device__ __forceinline__ float neg_log_ec(float idf) {
    // p = log((id+2)/(id+1)) / LOG_RANGE   (same f32 ratio form as reference)
    float p  = logf((idf + 2.0f) / (idf + 1.0f)) / LOG_RANGE;
    // ec = -expm1(S * log1p(-p))
    float ec = -expm1f(16384.0f * log1pf(-p));
    return -logf(ec);
}

__device__ __forceinline__ float sigmoid_xent(float l, float t) {
    // max(l,0) - l*t + log1p(exp(-|l|))
    return fmaxf(l, 0.0f) - l * t + log1pf(expf(-fabsf(l)));
}

// ---------------- kernel 0: per-sampled offset = bias - log(ec) -----------
__global__ void prep_sampled_kernel(const int* __restrict__ sampled,
                                    const float* __restrict__ bias) {
    int i = blockIdx.x * blockDim.x + threadIdx.x;
    if (i < NUM_SAMPLED) {
        int id = sampled[i];
        g_off_sampled[i] = bias[id] + neg_log_ec((float)id);
    }
}

// ---------------- kernel 1: sampled GEMM + softplus row-reduce ------------
// C[b,s] = inputs[b,:] . w[sampled[s],:] + off[s];  partial[bn][b] = sum_s softplus(C)
__global__ __launch_bounds__(256, 2)
void sampled_gemm_kernel(const float* __restrict__ A,   // [BATCH, DIM]
                         const float* __restrict__ W,   // [NUM_CLASSES, DIM]
                         const int*   __restrict__ sampled) {
    __shared__ float As[BK][BM];
    __shared__ float Bs[BK][BN];
    __shared__ int   sid[BN];
    __shared__ float soff[BN];
    __shared__ float red[BM][17];   // padded reduce buffer

    const int tid = threadIdx.x;
    const int bn  = blockIdx.x;            // 0..127 sampled tile
    const int bm  = blockIdx.y;            // 0..1 batch tile
    const int m0  = bm * BM;
    const int n0  = bn * BN;

    if (tid < BN) {
        sid[tid]  = sampled[n0 + tid];
        soff[tid] = g_off_sampled[n0 + tid];
    }
    __syncthreads();

    const int tx = tid & 15;               // 0..15 -> 8 cols
    const int ty = tid >> 4;               // 0..15 -> 8 rows
    const int lrow = tid >> 1;             // 0..127
    const int lc   = (tid & 1) * 4;        // 0 or 4

    const float* a_src = A + (m0 + lrow) * DIM + lc;
    const int    brow  = sid[lrow];
    const float* b_src = W + brow * DIM + lc;

    float acc[TM][TN];
#pragma unroll
    for (int i = 0; i < TM; i++)
#pragma unroll
        for (int j = 0; j < TN; j++) acc[i][j] = 0.0f;

    // preload k-tile 0
    float4 av = *(const float4*)(a_src);
    float4 bv = *(const float4*)(b_src);

    const int NKT = DIM / BK;   // 32
    for (int kt = 0; kt < NKT; kt++) {
        // store current tile (transposed) to smem
        As[lc + 0][lrow] = av.x; As[lc + 1][lrow] = av.y;
        As[lc + 2][lrow] = av.z; As[lc + 3][lrow] = av.w;
        Bs[lc + 0][lrow] = bv.x; Bs[lc + 1][lrow] = bv.y;
        Bs[lc + 2][lrow] = bv.z; Bs[lc + 3][lrow] = bv.w;
        __syncthreads();

        // prefetch next tile while computing
        if (kt + 1 < NKT) {
            av = *(const float4*)(a_src + (kt + 1) * BK);
            bv = *(const float4*)(b_src + (kt + 1) * BK);
        }

        float af[TM], bf[TN];
#pragma unroll
        for (int kk = 0; kk < BK; kk++) {
            *(float4*)&af[0] = *(const float4*)&As[kk][ty * 8];
            *(float4*)&af[4] = *(const float4*)&As[kk][ty * 8 + 4];
            *(float4*)&bf[0] = *(const float4*)&Bs[kk][tx * 8];
            *(float4*)&bf[4] = *(const float4*)&Bs[kk][tx * 8 + 4];
#pragma unroll
            for (int i = 0; i < TM; i++)
#pragma unroll
                for (int j = 0; j < TN; j++)
                    acc[i][j] = fmaf(af[i], bf[j], acc[i][j]);
        }
        __syncthreads();
    }

    // epilogue: logit -> softplus -> per-row sums
    float rowsum[TM];
#pragma unroll
    for (int i = 0; i < TM; i++) rowsum[i] = 0.0f;
#pragma unroll
    for (int i = 0; i < TM; i++) {
#pragma unroll
        for (int j = 0; j < TN; j++) {
            float l = acc[i][j] + soff[tx * 8 + j];
            // sigmoid_xent with target 0: max(l,0) + log1p(exp(-|l|))
            rowsum[i] += fmaxf(l, 0.0f) + log1pf(expf(-fabsf(l)));
        }
    }

#pragma unroll
    for (int i = 0; i < TM; i++) red[ty * 8 + i][tx] = rowsum[i];
    __syncthreads();

    if (tid < BM) {
        float s = 0.0f;
#pragma unroll
        for (int t = 0; t < 16; t++) s += red[tid][t];
        g_partial_sampled[bn * BATCH + m0 + tid] = s;
    }
}

// ---------------- kernel 2: true logits (gathered dots) -------------------
// grid (BATCH, 2); block 256 threads; each thread handles 2 labels.
__global__ __launch_bounds__(256)
void true_kernel(const float* __restrict__ A,
                 const float* __restrict__ W,
                 const float* __restrict__ bias,
                 const int*   __restrict__ labels) {
    const int b     = blockIdx.x;
    const int chunk = blockIdx.y;     // 0 or 1 -> labels [chunk*512, chunk*512+512)
    const int tid   = threadIdx.x;

    __shared__ float4 sin4[DIM / 4];
    if (tid < DIM / 4) sin4[tid] = ((const float4*)(A + b * DIM))[tid];
    __syncthreads();

    const int t0   = chunk * 512 + tid;
    const int lab0 = labels[b * NUM_TRUE + t0];
    const int lab1 = labels[b * NUM_TRUE + t0 + 256];
    const float4* w0 = (const float4*)(W + (size_t)lab0 * DIM);
    const float4* w1 = (const float4*)(W + (size_t)lab1 * DIM);

    float acc0 = 0.0f, acc1 = 0.0f;
#pragma unroll 8
    for (int k = 0; k < DIM / 4; k++) {
        float4 x = sin4[k];
        float4 u = w0[k];
        float4 v = w1[k];
        acc0 = fmaf(x.x, u.x, acc0); acc0 = fmaf(x.y, u.y, acc0);
        acc0 = fmaf(x.z, u.z, acc0); acc0 = fmaf(x.w, u.w, acc0);
        acc1 = fmaf(x.x, v.x, acc1); acc1 = fmaf(x.y, v.y, acc1);
        acc1 = fmaf(x.z, v.z, acc1); acc1 = fmaf(x.w, v.w, acc1);
    }

    const float tt = 1.0f / (float)NUM_TRUE;
    float l0 = acc0 + bias[lab0] + neg_log_ec((float)lab0);
    float l1 = acc1 + bias[lab1] + neg_log_ec((float)lab1);
    float s  = sigmoid_xent(l0, tt) + sigmoid_xent(l1, tt);

    __shared__ float red[256];
    red[tid] = s;
    __syncthreads();
#pragma unroll
    for (int off = 128; off > 0; off >>= 1) {
        if (tid < off) red[tid] += red[tid + off];
        __syncthreads();
    }
    if (tid == 0) g_true_part[chunk * BATCH + b] = red[0];
}

// ---------------- kernel 3: finalize --------------------------------------
__global__ void finalize_kernel(float* __restrict__ out) {
    int b = threadIdx.x;   // 256 threads, 1 block
    float s = g_true_part[b] + g_true_part[BATCH + b];
#pragma unroll 8
    for (int nb = 0; nb < NB_N; nb++) s += g_partial_sampled[nb * BATCH + b];
    out[b] = s;
}

// ---------------- launch ---------------------------------------------------
extern "C" void kernel_launch(void* const* d_in, const int* in_sizes, int n_in,
                              void* d_out, int out_size) {
    const float* inputs  = (const float*)d_in[0];   // [256,256]
    const float* w       = (const float*)d_in[1];   // [100000,256]
    const float* bias    = (const float*)d_in[2];   // [100000]
    const int*   labels  = (const int*)d_in[3];     // [256,1024]
    const int*   sampled = (const int*)d_in[4];     // [16384]
    float*       out     = (float*)d_out;           // [256]

    prep_sampled_kernel<<<(NUM_SAMPLED + 255) / 256, 256>>>(sampled, bias);
    sampled_gemm_kernel<<<dim3(NB_N, 2), 256>>>(inputs, w, sampled);
    true_kernel<<<dim3(BATCH, 2), 256>>>(inputs, w, bias, labels);
    finalize_kernel<<<1, 256>>>(out);
}

// round 2
// speedup vs baseline: 1.5159x; 1.5159x over previous
#include <cuda_runtime.h>
#include <cuda_bf16.h>
#include <cstdint>

// Problem constants
#define BATCH       256
#define DIM         256
#define NUM_TRUE    1024
#define NUM_SAMPLED 16384
#define LOG_RANGE   11.5129354649202280f

// GEMM tiling (bf16 tensor core)
#define BM   128
#define BN   128
#define BKT  32               // k per smem tile
#define NKT  (DIM / BKT)      // 8 k-tiles
#define NB_N (NUM_SAMPLED / BN)  // 128 n-blocks
#define PAD  40               // padded smem row (bf16 elems): 80B stride, ldmatrix conflict-free

// ---------------- device scratch (no allocations allowed) ----------------
__device__ __nv_bfloat16 g_Wg[NUM_SAMPLED * DIM];    // gathered w[sampled] in bf16 (8 MB)
__device__ __nv_bfloat16 g_Abf[BATCH * DIM];         // inputs in bf16
__device__ float g_off_sampled[NUM_SAMPLED];         // bias[sampled] - log(ec)
__device__ float g_partial[NB_N * BATCH];            // [n_block][b]
__device__ float g_true_part[2 * BATCH];             // [chunk][b]

// ---------------- math helpers (mirror reference numerics) ----------------
__device__ __forceinline__ float neg_log_ec(float idf) {
    float p  = logf((idf + 2.0f) / (idf + 1.0f)) / LOG_RANGE;
    float ec = -expm1f(16384.0f * log1pf(-p));
    return -logf(ec);
}
__device__ __forceinline__ float softplus0(float l) {   // xent with target 0
    return fmaxf(l, 0.0f) + log1pf(expf(-fabsf(l)));
}
__device__ __forceinline__ float sigmoid_xent(float l, float t) {
    return fmaxf(l, 0.0f) - l * t + log1pf(expf(-fabsf(l)));
}

// ---------------- PTX helpers ----------------
__device__ __forceinline__ void ldsm_x4(uint32_t& r0, uint32_t& r1, uint32_t& r2, uint32_t& r3,
                                        uint32_t addr) {
    asm volatile("ldmatrix.sync.aligned.m8n8.x4.shared.b16 {%0,%1,%2,%3}, [%4];\n"
                 : "=r"(r0), "=r"(r1), "=r"(r2), "=r"(r3) : "r"(addr));
}
__device__ __forceinline__ void mma16816(float* c,
                                         uint32_t a0, uint32_t a1, uint32_t a2, uint32_t a3,
                                         uint32_t b0, uint32_t b1) {
    asm volatile("mma.sync.aligned.m16n8k16.row.col.f32.bf16.bf16.f32 "
                 "{%0,%1,%2,%3}, {%4,%5,%6,%7}, {%8,%9}, {%0,%1,%2,%3};\n"
                 : "+f"(c[0]), "+f"(c[1]), "+f"(c[2]), "+f"(c[3])
                 : "r"(a0), "r"(a1), "r"(a2), "r"(a3), "r"(b0), "r"(b1));
}

// ---------------- kernel 0: gather + f32->bf16 convert + offsets ----------
// units: 4 floats each. Wg: 16384*64 units, then inputs: 256*64 units.
__global__ void convert_kernel(const float* __restrict__ inputs,
                               const float* __restrict__ w,
                               const float* __restrict__ bias,
                               const int*   __restrict__ sampled) {
    int u = blockIdx.x * blockDim.x + threadIdx.x;
    const int WG_UNITS = NUM_SAMPLED * (DIM / 4);
    if (u < WG_UNITS) {
        int row = u >> 6, q = u & 63;
        int id = __ldg(&sampled[row]);
        float4 v = __ldg((const float4*)(w + (size_t)id * DIM) + q);
        __nv_bfloat162* dst = (__nv_bfloat162*)(g_Wg + row * DIM + q * 4);
        dst[0] = __floats2bfloat162_rn(v.x, v.y);
        dst[1] = __floats2bfloat162_rn(v.z, v.w);
        if (q == 0) g_off_sampled[row] = bias[id] + neg_log_ec((float)id);
    } else {
        int u2 = u - WG_UNITS;
        if (u2 < BATCH * (DIM / 4)) {
            int row = u2 >> 6, q = u2 & 63;
            float4 v = __ldg((const float4*)(inputs + row * DIM) + q);
            __nv_bfloat162* dst = (__nv_bfloat162*)(g_Abf + row * DIM + q * 4);
            dst[0] = __floats2bfloat162_rn(v.x, v.y);
            dst[1] = __floats2bfloat162_rn(v.z, v.w);
        }
    }
}

// ---------------- kernel 1: bf16 tensor-core GEMM + softplus reduce -------
// C[b,s] = A[b,:].Wg[s,:] + off[s];  g_partial[bn][b] = sum_s softplus(C)
__global__ __launch_bounds__(256, 2)
void gemm_kernel() {
    __shared__ __nv_bfloat16 As[2][BM][PAD];
    __shared__ __nv_bfloat16 Bs[2][BN][PAD];
    __shared__ float soff_s[BN];
    __shared__ float red2[2][BM];

    const int tid  = threadIdx.x;
    const int lane = tid & 31;
    const int wid  = tid >> 5;
    const int bn   = blockIdx.x;
    const int bm   = blockIdx.y;
    const int m0   = bm * BM, n0 = bn * BN;

    if (tid < BN) soff_s[tid] = g_off_sampled[n0 + tid];

    // warp grid: 4 (m) x 2 (n); warp tile 32x64
    const int mw = (wid & 3) * 32;
    const int nw = (wid >> 2) * 64;
    const int warp_n = wid >> 2;

    // global load mapping: 512 uint4 per operand per tile; 2 per thread
    const int lr0 = tid >> 2;   // rows 0..63 (unit0), +64 (unit1)
    const int lc  = tid & 3;    // 16B chunk within 64B row-slice
    const uint4* gA0 = (const uint4*)(g_Abf + (m0 + lr0) * DIM) + lc;
    const uint4* gA1 = (const uint4*)(g_Abf + (m0 + lr0 + 64) * DIM) + lc;
    const uint4* gB0 = (const uint4*)(g_Wg + (n0 + lr0) * DIM) + lc;
    const uint4* gB1 = (const uint4*)(g_Wg + (n0 + lr0 + 64) * DIM) + lc;

    float c[2][8][4];
#pragma unroll
    for (int i = 0; i < 2; i++)
#pragma unroll
        for (int j = 0; j < 8; j++)
#pragma unroll
            for (int e = 0; e < 4; e++) c[i][j][e] = 0.0f;

    // stage 0
    uint4 ra0 = gA0[0], ra1 = gA1[0], rb0 = gB0[0], rb1 = gB1[0];
    *(uint4*)&As[0][lr0][lc * 8]      = ra0;
    *(uint4*)&As[0][lr0 + 64][lc * 8] = ra1;
    *(uint4*)&Bs[0][lr0][lc * 8]      = rb0;
    *(uint4*)&Bs[0][lr0 + 64][lc * 8] = rb1;
    __syncthreads();

    const uint32_t sAs = (uint32_t)__cvta_generic_to_shared(&As[0][0][0]);
    const uint32_t sBs = (uint32_t)__cvta_generic_to_shared(&Bs[0][0][0]);
    const uint32_t bufbytes = BM * PAD * 2;

    int buf = 0;
    for (int kt = 0; kt < NKT; kt++) {
        if (kt < NKT - 1) {   // prefetch next k-tile into regs
            ra0 = gA0[(kt + 1) * 4]; ra1 = gA1[(kt + 1) * 4];
            rb0 = gB0[(kt + 1) * 4]; rb1 = gB1[(kt + 1) * 4];
        }
        const uint32_t baseA = sAs + buf * bufbytes;
        const uint32_t baseB = sBs + buf * bufbytes;
#pragma unroll
        for (int ks = 0; ks < 2; ks++) {
            uint32_t a[2][4], b[4][4];
#pragma unroll
            for (int mt = 0; mt < 2; mt++) {
                uint32_t addr = baseA +
                    ((mw + mt * 16 + (lane & 15)) * PAD + ks * 16 + (lane >> 4) * 8) * 2;
                ldsm_x4(a[mt][0], a[mt][1], a[mt][2], a[mt][3], addr);
            }
#pragma unroll
            for (int p = 0; p < 4; p++) {
                uint32_t addr = baseB +
                    ((nw + p * 16 + (lane & 7) + ((lane >> 4) & 1) * 8) * PAD +
                     ks * 16 + ((lane >> 3) & 1) * 8) * 2;
                ldsm_x4(b[p][0], b[p][1], b[p][2], b[p][3], addr);
            }
#pragma unroll
            for (int mt = 0; mt < 2; mt++)
#pragma unroll
                for (int nt = 0; nt < 8; nt++) {
                    int p = nt >> 1, h = nt & 1;
                    mma16816(c[mt][nt], a[mt][0], a[mt][1], a[mt][2], a[mt][3],
                             b[p][h * 2], b[p][h * 2 + 1]);
                }
        }
        if (kt < NKT - 1) {
            int nb = buf ^ 1;
            *(uint4*)&As[nb][lr0][lc * 8]      = ra0;
            *(uint4*)&As[nb][lr0 + 64][lc * 8] = ra1;
            *(uint4*)&Bs[nb][lr0][lc * 8]      = rb0;
            *(uint4*)&Bs[nb][lr0 + 64][lc * 8] = rb1;
            __syncthreads();
            buf = nb;
        }
    }

    // epilogue: + offset, softplus, per-row sums
    float rs[4] = {0.f, 0.f, 0.f, 0.f};   // rows: mw + mt*16 + lane/4 + h*8
#pragma unroll
    for (int mt = 0; mt < 2; mt++)
#pragma unroll
        for (int nt = 0; nt < 8; nt++) {
            int colbase = nw + nt * 8 + (lane & 3) * 2;
#pragma unroll
            for (int e = 0; e < 4; e++) {
                float l = c[mt][nt][e] + soff_s[colbase + (e & 1)];
                rs[mt * 2 + (e >> 1)] += softplus0(l);
            }
        }
#pragma unroll
    for (int i = 0; i < 4; i++) {
        rs[i] += __shfl_xor_sync(0xffffffff, rs[i], 1);
        rs[i] += __shfl_xor_sync(0xffffffff, rs[i], 2);
    }
    if ((lane & 3) == 0) {
        int r = lane >> 2;
        red2[warp_n][mw + r]          = rs[0];
        red2[warp_n][mw + r + 8]      = rs[1];
        red2[warp_n][mw + 16 + r]     = rs[2];
        red2[warp_n][mw + 16 + r + 8] = rs[3];
    }
    __syncthreads();
    if (tid < BM)
        g_partial[bn * BATCH + m0 + tid] = red2[0][tid] + red2[1][tid];
}

// ---------------- kernel 2: true logits (gathered dots) -------------------
__global__ __launch_bounds__(256)
void true_kernel(const float* __restrict__ A,
                 const float* __restrict__ W,
                 const float* __restrict__ bias,
                 const int*   __restrict__ labels) {
    const int b     = blockIdx.x;
    const int chunk = blockIdx.y;
    const int tid   = threadIdx.x;

    __shared__ float4 sin4[DIM / 4];
    if (tid < DIM / 4) sin4[tid] = ((const float4*)(A + b * DIM))[tid];
    __syncthreads();

    const int t0   = chunk * 512 + tid;
    const int lab0 = labels[b * NUM_TRUE + t0];
    const int lab1 = labels[b * NUM_TRUE + t0 + 256];
    const float4* w0 = (const float4*)(W + (size_t)lab0 * DIM);
    const float4* w1 = (const float4*)(W + (size_t)lab1 * DIM);

    float acc0 = 0.0f, acc1 = 0.0f;
#pragma unroll 8
    for (int k = 0; k < DIM / 4; k++) {
        float4 x = sin4[k];
        float4 u = w0[k];
        float4 v = w1[k];
        acc0 = fmaf(x.x, u.x, acc0); acc0 = fmaf(x.y, u.y, acc0);
        acc0 = fmaf(x.z, u.z, acc0); acc0 = fmaf(x.w, u.w, acc0);
        acc1 = fmaf(x.x, v.x, acc1); acc1 = fmaf(x.y, v.y, acc1);
        acc1 = fmaf(x.z, v.z, acc1); acc1 = fmaf(x.w, v.w, acc1);
    }

    const float tt = 1.0f / (float)NUM_TRUE;
    float l0 = acc0 + bias[lab0] + neg_log_ec((float)lab0);
    float l1 = acc1 + bias[lab1] + neg_log_ec((float)lab1);
    float s  = sigmoid_xent(l0, tt) + sigmoid_xent(l1, tt);

    __shared__ float red[256];
    red[tid] = s;
    __syncthreads();
#pragma unroll
    for (int off = 128; off > 0; off >>= 1) {
        if (tid < off) red[tid] += red[tid + off];
        __syncthreads();
    }
    if (tid == 0) g_true_part[chunk * BATCH + b] = red[0];
}

// ---------------- kernel 3: finalize (parallel) ----------------------------
__global__ void finalize_kernel(float* __restrict__ out) {
    const int b = blockIdx.x;     // 256 blocks
    const int t = threadIdx.x;    // 128 threads = NB_N
    float s = g_partial[t * BATCH + b];
#pragma unroll
    for (int o = 16; o > 0; o >>= 1) s += __shfl_xor_sync(0xffffffff, s, o);
    __shared__ float sm[4];
    if ((t & 31) == 0) sm[t >> 5] = s;
    __syncthreads();
    if (t == 0)
        out[b] = sm[0] + sm[1] + sm[2] + sm[3] + g_true_part[b] + g_true_part[BATCH + b];
}

// ---------------- launch ---------------------------------------------------
extern "C" void kernel_launch(void* const* d_in, const int* in_sizes, int n_in,
                              void* d_out, int out_size) {
    const float* inputs  = (const float*)d_in[0];
    const float* w       = (const float*)d_in[1];
    const float* bias    = (const float*)d_in[2];
    const int*   labels  = (const int*)d_in[3];
    const int*   sampled = (const int*)d_in[4];
    float*       out     = (float*)d_out;

    const int conv_units = (NUM_SAMPLED + BATCH) * (DIM / 4);
    convert_kernel<<<(conv_units + 255) / 256, 256>>>(inputs, w, bias, sampled);
    gemm_kernel<<<dim3(NB_N, BATCH / BM), 256>>>();
    true_kernel<<<dim3(BATCH, 2), 256>>>(inputs, w, bias, labels);
    finalize_kernel<<<BATCH, 128>>>(out);
}

// round 3
// speedup vs baseline: 2.5607x; 1.6893x over previous
#include <cuda_runtime.h>
#include <cuda_bf16.h>
#include <cstdint>

// Problem constants
#define BATCH       256
#define DIM         256
#define NUM_TRUE    1024
#define NUM_SAMPLED 16384
#define LOG_RANGE   11.5129354649202280f

// GEMM tiling (bf16 tensor core)
#define BM   128
#define BN   128
#define NKT  8                    // k-tiles of 32
#define NB_N (NUM_SAMPLED / BN)   // 128 n-blocks
#define PAD  40                   // padded smem row (bf16): 80B stride

// ---------------- device scratch ----------------
__device__ __nv_bfloat16 g_Wg[NUM_SAMPLED * DIM];
__device__ __nv_bfloat16 g_Abf[BATCH * DIM];
__device__ float g_off_sampled[NUM_SAMPLED];

// ---------------- math helpers (mirror reference numerics) ----------------
__device__ __forceinline__ float neg_log_ec(float idf) {
    float p  = logf((idf + 2.0f) / (idf + 1.0f)) / LOG_RANGE;
    float ec = -expm1f(16384.0f * log1pf(-p));
    return -logf(ec);
}
__device__ __forceinline__ float softplus0(float l) {
    return fmaxf(l, 0.0f) + log1pf(expf(-fabsf(l)));
}
__device__ __forceinline__ float sigmoid_xent(float l, float t) {
    return fmaxf(l, 0.0f) - l * t + log1pf(expf(-fabsf(l)));
}

// ---------------- PTX helpers ----------------
__device__ __forceinline__ void ldsm_x4(uint32_t& r0, uint32_t& r1, uint32_t& r2, uint32_t& r3,
                                        uint32_t addr) {
    asm volatile("ldmatrix.sync.aligned.m8n8.x4.shared.b16 {%0,%1,%2,%3}, [%4];\n"
                 : "=r"(r0), "=r"(r1), "=r"(r2), "=r"(r3) : "r"(addr));
}
__device__ __forceinline__ void mma16816(float* c,
                                         uint32_t a0, uint32_t a1, uint32_t a2, uint32_t a3,
                                         uint32_t b0, uint32_t b1) {
    asm volatile("mma.sync.aligned.m16n8k16.row.col.f32.bf16.bf16.f32 "
                 "{%0,%1,%2,%3}, {%4,%5,%6,%7}, {%8,%9}, {%0,%1,%2,%3};\n"
                 : "+f"(c[0]), "+f"(c[1]), "+f"(c[2]), "+f"(c[3])
                 : "r"(a0), "r"(a1), "r"(a2), "r"(a3), "r"(b0), "r"(b1));
}

// ---------------- kernel 0: gather+convert W, convert A, offsets, zero out ----
#define WG_UNITS (NUM_SAMPLED * (DIM / 4))
#define A_UNITS  (BATCH * (DIM / 4))
__global__ void convert_kernel(const float* __restrict__ inputs,
                               const float* __restrict__ w,
                               const float* __restrict__ bias,
                               const int*   __restrict__ sampled,
                               float*       __restrict__ out) {
    int u = blockIdx.x * blockDim.x + threadIdx.x;
    if (u < WG_UNITS) {
        int row = u >> 6, q = u & 63;
        int id = __ldg(&sampled[row]);
        float4 v = __ldg((const float4*)(w + (size_t)id * DIM) + q);
        __nv_bfloat162* dst = (__nv_bfloat162*)(g_Wg + row * DIM + q * 4);
        dst[0] = __floats2bfloat162_rn(v.x, v.y);
        dst[1] = __floats2bfloat162_rn(v.z, v.w);
        if (q == 0) g_off_sampled[row] = bias[id] + neg_log_ec((float)id);
    } else if (u < WG_UNITS + A_UNITS) {
        int u2 = u - WG_UNITS;
        int row = u2 >> 6, q = u2 & 63;
        float4 v = __ldg((const float4*)(inputs + row * DIM) + q);
        __nv_bfloat162* dst = (__nv_bfloat162*)(g_Abf + row * DIM + q * 4);
        dst[0] = __floats2bfloat162_rn(v.x, v.y);
        dst[1] = __floats2bfloat162_rn(v.z, v.w);
    } else if (u < WG_UNITS + A_UNITS + BATCH) {
        out[u - WG_UNITS - A_UNITS] = 0.0f;
    }
}

// ---------------- fused kernel: GEMM blocks (even) + true-gather blocks (odd) ----
struct GemmSmem {
    __nv_bfloat16 As[2][BM][PAD];
    __nv_bfloat16 Bs[2][BM][PAD];
    float soff[BN];
    float red2[2][BM];
};
union SmemU {
    GemmSmem g;
    float tred[8];
};

__global__ __launch_bounds__(256, 2)
void fused_kernel(const float* __restrict__ A,
                  const float* __restrict__ W,
                  const float* __restrict__ bias,
                  const int*   __restrict__ labels,
                  float*       __restrict__ out) {
    __shared__ SmemU sm;
    const int blk = blockIdx.x;
    const int tid = threadIdx.x;
    const int lane = tid & 31;
    const int wid  = tid >> 5;

    if ((blk & 1) == 0) {
        // ================= GEMM path =================
        const int id = blk >> 1;          // 0..255
        const int bn = id & 127;
        const int bm = id >> 7;
        const int m0 = bm * BM, n0 = bn * BN;

        if (tid < BN) sm.g.soff[tid] = g_off_sampled[n0 + tid];

        const int mw = (wid & 3) * 32;
        const int nw = (wid >> 2) * 64;
        const int warp_n = wid >> 2;

        const int lr0 = tid >> 2;
        const int lc  = tid & 3;
        const uint4* gA0 = (const uint4*)(g_Abf + (m0 + lr0) * DIM) + lc;
        const uint4* gA1 = (const uint4*)(g_Abf + (m0 + lr0 + 64) * DIM) + lc;
        const uint4* gB0 = (const uint4*)(g_Wg + (n0 + lr0) * DIM) + lc;
        const uint4* gB1 = (const uint4*)(g_Wg + (n0 + lr0 + 64) * DIM) + lc;

        float c[2][8][4];
#pragma unroll
        for (int i = 0; i < 2; i++)
#pragma unroll
            for (int j = 0; j < 8; j++)
#pragma unroll
                for (int e = 0; e < 4; e++) c[i][j][e] = 0.0f;

        uint4 ra0 = gA0[0], ra1 = gA1[0], rb0 = gB0[0], rb1 = gB1[0];
        *(uint4*)&sm.g.As[0][lr0][lc * 8]      = ra0;
        *(uint4*)&sm.g.As[0][lr0 + 64][lc * 8] = ra1;
        *(uint4*)&sm.g.Bs[0][lr0][lc * 8]      = rb0;
        *(uint4*)&sm.g.Bs[0][lr0 + 64][lc * 8] = rb1;
        __syncthreads();

        const uint32_t sAs = (uint32_t)__cvta_generic_to_shared(&sm.g.As[0][0][0]);
        const uint32_t sBs = (uint32_t)__cvta_generic_to_shared(&sm.g.Bs[0][0][0]);
        const uint32_t bufbytes = BM * PAD * 2;

        int buf = 0;
        for (int kt = 0; kt < NKT; kt++) {
            if (kt < NKT - 1) {
                ra0 = gA0[(kt + 1) * 4]; ra1 = gA1[(kt + 1) * 4];
                rb0 = gB0[(kt + 1) * 4]; rb1 = gB1[(kt + 1) * 4];
            }
            const uint32_t baseA = sAs + buf * bufbytes;
            const uint32_t baseB = sBs + buf * bufbytes;
#pragma unroll
            for (int ks = 0; ks < 2; ks++) {
                uint32_t a[2][4], b[4][4];
#pragma unroll
                for (int mt = 0; mt < 2; mt++) {
                    uint32_t addr = baseA +
                        ((mw + mt * 16 + (lane & 15)) * PAD + ks * 16 + (lane >> 4) * 8) * 2;
                    ldsm_x4(a[mt][0], a[mt][1], a[mt][2], a[mt][3], addr);
                }
#pragma unroll
                for (int p = 0; p < 4; p++) {
                    uint32_t addr = baseB +
                        ((nw + p * 16 + (lane & 7) + ((lane >> 4) & 1) * 8) * PAD +
                         ks * 16 + ((lane >> 3) & 1) * 8) * 2;
                    ldsm_x4(b[p][0], b[p][1], b[p][2], b[p][3], addr);
                }
#pragma unroll
                for (int mt = 0; mt < 2; mt++)
#pragma unroll
                    for (int nt = 0; nt < 8; nt++) {
                        int p = nt >> 1, h = nt & 1;
                        mma16816(c[mt][nt], a[mt][0], a[mt][1], a[mt][2], a[mt][3],
                                 b[p][h * 2], b[p][h * 2 + 1]);
                    }
            }
            if (kt < NKT - 1) {
                int nb = buf ^ 1;
                *(uint4*)&sm.g.As[nb][lr0][lc * 8]      = ra0;
                *(uint4*)&sm.g.As[nb][lr0 + 64][lc * 8] = ra1;
                *(uint4*)&sm.g.Bs[nb][lr0][lc * 8]      = rb0;
                *(uint4*)&sm.g.Bs[nb][lr0 + 64][lc * 8] = rb1;
                __syncthreads();
                buf = nb;
            }
        }

        float rs[4] = {0.f, 0.f, 0.f, 0.f};
#pragma unroll
        for (int mt = 0; mt < 2; mt++)
#pragma unroll
            for (int nt = 0; nt < 8; nt++) {
                int colbase = nw + nt * 8 + (lane & 3) * 2;
#pragma unroll
                for (int e = 0; e < 4; e++) {
                    float l = c[mt][nt][e] + sm.g.soff[colbase + (e & 1)];
                    rs[mt * 2 + (e >> 1)] += softplus0(l);
                }
            }
#pragma unroll
        for (int i = 0; i < 4; i++) {
            rs[i] += __shfl_xor_sync(0xffffffff, rs[i], 1);
            rs[i] += __shfl_xor_sync(0xffffffff, rs[i], 2);
        }
        if ((lane & 3) == 0) {
            int r = lane >> 2;
            sm.g.red2[warp_n][mw + r]          = rs[0];
            sm.g.red2[warp_n][mw + r + 8]      = rs[1];
            sm.g.red2[warp_n][mw + 16 + r]     = rs[2];
            sm.g.red2[warp_n][mw + 16 + r + 8] = rs[3];
        }
        __syncthreads();
        if (tid < BM)
            atomicAdd(out + m0 + tid, sm.g.red2[0][tid] + sm.g.red2[1][tid]);
    } else {
        // ================= true-logits path =================
        // One block per batch row; warp w handles labels [w*128, w*128+128).
        const int b = blk >> 1;   // 0..255

        // input row in registers (coalesced)
        const float4* arow = (const float4*)(A + b * DIM);
        const float4 x0 = __ldg(arow + lane);
        const float4 x1 = __ldg(arow + lane + 32);

        const int* lab_base = labels + b * NUM_TRUE + wid * 128;
        const float tt = 1.0f / (float)NUM_TRUE;

        float acc = 0.0f;
#pragma unroll
        for (int g = 0; g < 4; g++) {
            const int labv = __ldg(lab_base + g * 32 + lane);   // my group's label
            float mylogit = 0.0f;
#pragma unroll 8
            for (int j = 0; j < 32; j++) {
                int lab = __shfl_sync(0xffffffff, labv, j);
                const float4* wr = (const float4*)(W + (size_t)lab * DIM);
                float4 u0 = __ldg(wr + lane);
                float4 u1 = __ldg(wr + lane + 32);
                float d = x0.x * u0.x;
                d = fmaf(x0.y, u0.y, d); d = fmaf(x0.z, u0.z, d); d = fmaf(x0.w, u0.w, d);
                d = fmaf(x1.x, u1.x, d); d = fmaf(x1.y, u1.y, d);
                d = fmaf(x1.z, u1.z, d); d = fmaf(x1.w, u1.w, d);
                d += __shfl_xor_sync(0xffffffff, d, 16);
                d += __shfl_xor_sync(0xffffffff, d, 8);
                d += __shfl_xor_sync(0xffffffff, d, 4);
                d += __shfl_xor_sync(0xffffffff, d, 2);
                d += __shfl_xor_sync(0xffffffff, d, 1);
                if (lane == j) mylogit = d;
            }
            // lane-parallel xent for this group's 32 labels
            float l = mylogit + __ldg(bias + labv) + neg_log_ec((float)labv);
            acc += sigmoid_xent(l, tt);
        }
        // reduce warp accs -> block -> one atomic
        acc += __shfl_xor_sync(0xffffffff, acc, 16);
        acc += __shfl_xor_sync(0xffffffff, acc, 8);
        acc += __shfl_xor_sync(0xffffffff, acc, 4);
        acc += __shfl_xor_sync(0xffffffff, acc, 2);
        acc += __shfl_xor_sync(0xffffffff, acc, 1);
        if (lane == 0) sm.tred[wid] = acc;
        __syncthreads();
        if (tid == 0) {
            float s = 0.0f;
#pragma unroll
            for (int i = 0; i < 8; i++) s += sm.tred[i];
            atomicAdd(out + b, s);
        }
    }
}

// ---------------- launch ---------------------------------------------------
extern "C" void kernel_launch(void* const* d_in, const int* in_sizes, int n_in,
                              void* d_out, int out_size) {
    const float* inputs  = (const float*)d_in[0];
    const float* w       = (const float*)d_in[1];
    const float* bias    = (const float*)d_in[2];
    const int*   labels  = (const int*)d_in[3];
    const int*   sampled = (const int*)d_in[4];
    float*       out     = (float*)d_out;

    const int conv_units = WG_UNITS + A_UNITS + BATCH;
    convert_kernel<<<(conv_units + 255) / 256, 256>>>(inputs, w, bias, sampled, out);
    fused_kernel<<<512, 256>>>(inputs, w, bias, labels, out);
}

// round 4
// speedup vs baseline: 2.7896x; 1.0894x over previous
#include <cuda_runtime.h>
#include <cuda_bf16.h>
#include <cstdint>

// Problem constants
#define BATCH       256
#define DIM         256
#define NUM_TRUE    1024
#define NUM_SAMPLED 16384
#define LOG_RANGE   11.5129354649202280f

// GEMM tiling (bf16 tensor core): block tile 128(m) x 64(n), k-tiles of 32
#define BM   128
#define BN   64
#define NKT  8
#define NBN  (NUM_SAMPLED / BN)     // 256 n-blocks
#define NGEMM (NBN * (BATCH / BM))  // 512 gemm blocks
#define PAD  40                     // padded smem row (bf16): 80B stride

// ---------------- device scratch ----------------
__device__ __nv_bfloat16 g_Wg[NUM_SAMPLED * DIM];
__device__ __nv_bfloat16 g_Abf[BATCH * DIM];
__device__ float g_off_sampled[NUM_SAMPLED];

// ---------------- math helpers (mirror reference numerics) ----------------
__device__ __forceinline__ float neg_log_ec(float idf) {
    float p  = logf((idf + 2.0f) / (idf + 1.0f)) / LOG_RANGE;
    float ec = -expm1f(16384.0f * log1pf(-p));
    return -logf(ec);
}
__device__ __forceinline__ float softplus0(float l) {
    return fmaxf(l, 0.0f) + log1pf(expf(-fabsf(l)));
}
__device__ __forceinline__ float sigmoid_xent(float l, float t) {
    return fmaxf(l, 0.0f) - l * t + log1pf(expf(-fabsf(l)));
}

// ---------------- PTX helpers ----------------
__device__ __forceinline__ void ldsm_x4(uint32_t& r0, uint32_t& r1, uint32_t& r2, uint32_t& r3,
                                        uint32_t addr) {
    asm volatile("ldmatrix.sync.aligned.m8n8.x4.shared.b16 {%0,%1,%2,%3}, [%4];\n"
                 : "=r"(r0), "=r"(r1), "=r"(r2), "=r"(r3) : "r"(addr));
}
__device__ __forceinline__ void mma16816(float* c,
                                         uint32_t a0, uint32_t a1, uint32_t a2, uint32_t a3,
                                         uint32_t b0, uint32_t b1) {
    asm volatile("mma.sync.aligned.m16n8k16.row.col.f32.bf16.bf16.f32 "
                 "{%0,%1,%2,%3}, {%4,%5,%6,%7}, {%8,%9}, {%0,%1,%2,%3};\n"
                 : "+f"(c[0]), "+f"(c[1]), "+f"(c[2]), "+f"(c[3])
                 : "r"(a0), "r"(a1), "r"(a2), "r"(a3), "r"(b0), "r"(b1));
}

// ---------------- kernel 0: gather+convert W, convert A, offsets, zero out ----
#define WG_UNITS (NUM_SAMPLED * (DIM / 4))
#define A_UNITS  (BATCH * (DIM / 4))
__global__ void convert_kernel(const float* __restrict__ inputs,
                               const float* __restrict__ w,
                               const float* __restrict__ bias,
                               const int*   __restrict__ sampled,
                               float*       __restrict__ out) {
    int u = blockIdx.x * blockDim.x + threadIdx.x;
    if (u < WG_UNITS) {
        int row = u >> 6, q = u & 63;
        int id = __ldg(&sampled[row]);
        float4 v = __ldg((const float4*)(w + (size_t)id * DIM) + q);
        __nv_bfloat162* dst = (__nv_bfloat162*)(g_Wg + row * DIM + q * 4);
        dst[0] = __floats2bfloat162_rn(v.x, v.y);
        dst[1] = __floats2bfloat162_rn(v.z, v.w);
        if (q == 0) g_off_sampled[row] = bias[id] + neg_log_ec((float)id);
    } else if (u < WG_UNITS + A_UNITS) {
        int u2 = u - WG_UNITS;
        int row = u2 >> 6, q = u2 & 63;
        float4 v = __ldg((const float4*)(inputs + row * DIM) + q);
        __nv_bfloat162* dst = (__nv_bfloat162*)(g_Abf + row * DIM + q * 4);
        dst[0] = __floats2bfloat162_rn(v.x, v.y);
        dst[1] = __floats2bfloat162_rn(v.z, v.w);
    } else if (u < WG_UNITS + A_UNITS + BATCH) {
        out[u - WG_UNITS - A_UNITS] = 0.0f;
    }
}

// ---------------- fused kernel -------------------------------------------
struct GemmSmem {
    __nv_bfloat16 As[2][BM][PAD];
    __nv_bfloat16 Bs[2][BN][PAD];
    float soff[BN];
    float red2[2][BM];
};
union SmemU {
    GemmSmem g;
    float tred[8];
};

__global__ __launch_bounds__(256, 3)
void fused_kernel(const float* __restrict__ A,
                  const float* __restrict__ W,
                  const float* __restrict__ bias,
                  const int*   __restrict__ labels,
                  float*       __restrict__ out) {
    __shared__ SmemU sm;
    const int blk  = blockIdx.x;
    const int tid  = threadIdx.x;
    const int lane = tid & 31;
    const int wid  = tid >> 5;

    const int role = blk % 3;       // 0,1 -> GEMM; 2 -> true
    const int base = blk / 3;       // 0..255

    if (role < 2) {
        // ================= GEMM path: tile BM=128 x BN=64 =================
        const int id = base * 2 + role;     // 0..511
        const int bn = id >> 1;             // 0..255
        const int bm = id & 1;              // 0..1
        const int m0 = bm * BM, n0 = bn * BN;

        if (tid < BN) sm.g.soff[tid] = g_off_sampled[n0 + tid];

        // warp grid: 4 (m) x 2 (n); warp tile 32x32
        const int mw = (wid >> 1) * 32;
        const int nw = (wid & 1) * 32;
        const int nwarp = wid & 1;

        // global loaders: A 128x32 bf16 (512 x 16B, 2/thr); B 64x32 (256, 1/thr)
        const int lr0 = tid >> 2;   // 0..63
        const int lc  = tid & 3;
        const uint4* gA0 = (const uint4*)(g_Abf + (m0 + lr0) * DIM) + lc;
        const uint4* gA1 = (const uint4*)(g_Abf + (m0 + lr0 + 64) * DIM) + lc;
        const uint4* gB0 = (const uint4*)(g_Wg + (n0 + lr0) * DIM) + lc;

        float c[2][4][4];
#pragma unroll
        for (int i = 0; i < 2; i++)
#pragma unroll
            for (int j = 0; j < 4; j++)
#pragma unroll
                for (int e = 0; e < 4; e++) c[i][j][e] = 0.0f;

        uint4 ra0 = gA0[0], ra1 = gA1[0], rb0 = gB0[0];
        *(uint4*)&sm.g.As[0][lr0][lc * 8]      = ra0;
        *(uint4*)&sm.g.As[0][lr0 + 64][lc * 8] = ra1;
        *(uint4*)&sm.g.Bs[0][lr0][lc * 8]      = rb0;
        __syncthreads();

        const uint32_t sAs = (uint32_t)__cvta_generic_to_shared(&sm.g.As[0][0][0]);
        const uint32_t sBs = (uint32_t)__cvta_generic_to_shared(&sm.g.Bs[0][0][0]);
        const uint32_t abuf = BM * PAD * 2;
        const uint32_t bbuf = BN * PAD * 2;

        int buf = 0;
        for (int kt = 0; kt < NKT; kt++) {
            if (kt < NKT - 1) {
                ra0 = gA0[(kt + 1) * 4];
                ra1 = gA1[(kt + 1) * 4];
                rb0 = gB0[(kt + 1) * 4];
            }
            const uint32_t baseA = sAs + buf * abuf;
            const uint32_t baseB = sBs + buf * bbuf;
#pragma unroll
            for (int ks = 0; ks < 2; ks++) {
                uint32_t a[2][4], b[2][4];
#pragma unroll
                for (int mt = 0; mt < 2; mt++) {
                    uint32_t addr = baseA +
                        ((mw + mt * 16 + (lane & 15)) * PAD + ks * 16 + (lane >> 4) * 8) * 2;
                    ldsm_x4(a[mt][0], a[mt][1], a[mt][2], a[mt][3], addr);
                }
#pragma unroll
                for (int p = 0; p < 2; p++) {
                    uint32_t addr = baseB +
                        ((nw + p * 16 + (lane & 7) + ((lane >> 4) & 1) * 8) * PAD +
                         ks * 16 + ((lane >> 3) & 1) * 8) * 2;
                    ldsm_x4(b[p][0], b[p][1], b[p][2], b[p][3], addr);
                }
#pragma unroll
                for (int mt = 0; mt < 2; mt++)
#pragma unroll
                    for (int nt = 0; nt < 4; nt++) {
                        int p = nt >> 1, h = nt & 1;
                        mma16816(c[mt][nt], a[mt][0], a[mt][1], a[mt][2], a[mt][3],
                                 b[p][h * 2], b[p][h * 2 + 1]);
                    }
            }
            if (kt < NKT - 1) {
                int nb = buf ^ 1;
                *(uint4*)&sm.g.As[nb][lr0][lc * 8]      = ra0;
                *(uint4*)&sm.g.As[nb][lr0 + 64][lc * 8] = ra1;
                *(uint4*)&sm.g.Bs[nb][lr0][lc * 8]      = rb0;
                __syncthreads();
                buf = nb;
            }
        }

        // epilogue: +offset, softplus, per-row sums
        float rs[4] = {0.f, 0.f, 0.f, 0.f};
#pragma unroll
        for (int mt = 0; mt < 2; mt++)
#pragma unroll
            for (int nt = 0; nt < 4; nt++) {
                int colbase = nw + nt * 8 + (lane & 3) * 2;
#pragma unroll
                for (int e = 0; e < 4; e++) {
                    float l = c[mt][nt][e] + sm.g.soff[colbase + (e & 1)];
                    rs[mt * 2 + (e >> 1)] += softplus0(l);
                }
            }
#pragma unroll
        for (int i = 0; i < 4; i++) {
            rs[i] += __shfl_xor_sync(0xffffffff, rs[i], 1);
            rs[i] += __shfl_xor_sync(0xffffffff, rs[i], 2);
        }
        if ((lane & 3) == 0) {
            int r = lane >> 2;
            sm.g.red2[nwarp][mw + r]          = rs[0];
            sm.g.red2[nwarp][mw + r + 8]      = rs[1];
            sm.g.red2[nwarp][mw + 16 + r]     = rs[2];
            sm.g.red2[nwarp][mw + 16 + r + 8] = rs[3];
        }
        __syncthreads();
        if (tid < BM)
            atomicAdd(out + m0 + tid, sm.g.red2[0][tid] + sm.g.red2[1][tid]);
    } else {
        // ================= true-logits path =================
        const int b = base;

        const float4* arow = (const float4*)(A + b * DIM);
        const float4 x0 = __ldg(arow + lane);
        const float4 x1 = __ldg(arow + lane + 32);

        const int* lab_base = labels + b * NUM_TRUE + wid * 128;
        const float tt = 1.0f / (float)NUM_TRUE;

        float acc = 0.0f;
#pragma unroll
        for (int g = 0; g < 4; g++) {
            const int labv = __ldg(lab_base + g * 32 + lane);
            const float biasv = __ldg(bias + labv);
            float mylogit = 0.0f;
#pragma unroll 4
            for (int jp = 0; jp < 16; jp++) {
                int lab0 = __shfl_sync(0xffffffff, labv, jp);
                int lab1 = __shfl_sync(0xffffffff, labv, jp + 16);
                const float4* wr0 = (const float4*)(W + (size_t)lab0 * DIM);
                const float4* wr1 = (const float4*)(W + (size_t)lab1 * DIM);
                float4 u0a = __ldg(wr0 + lane);
                float4 u0b = __ldg(wr0 + lane + 32);
                float4 u1a = __ldg(wr1 + lane);
                float4 u1b = __ldg(wr1 + lane + 32);
                float d0 = x0.x * u0a.x;
                d0 = fmaf(x0.y, u0a.y, d0); d0 = fmaf(x0.z, u0a.z, d0);
                d0 = fmaf(x0.w, u0a.w, d0);
                d0 = fmaf(x1.x, u0b.x, d0); d0 = fmaf(x1.y, u0b.y, d0);
                d0 = fmaf(x1.z, u0b.z, d0); d0 = fmaf(x1.w, u0b.w, d0);
                float d1 = x0.x * u1a.x;
                d1 = fmaf(x0.y, u1a.y, d1); d1 = fmaf(x0.z, u1a.z, d1);
                d1 = fmaf(x0.w, u1a.w, d1);
                d1 = fmaf(x1.x, u1b.x, d1); d1 = fmaf(x1.y, u1b.y, d1);
                d1 = fmaf(x1.z, u1b.z, d1); d1 = fmaf(x1.w, u1b.w, d1);
                // pair reduce: 6 shfl for 2 labels
                d0 += __shfl_xor_sync(0xffffffff, d0, 16);
                d1 += __shfl_xor_sync(0xffffffff, d1, 16);
                float m = (lane < 16) ? d0 : d1;
                m += __shfl_xor_sync(0xffffffff, m, 8);
                m += __shfl_xor_sync(0xffffffff, m, 4);
                m += __shfl_xor_sync(0xffffffff, m, 2);
                m += __shfl_xor_sync(0xffffffff, m, 1);
                // lanes 0-15 hold sum(d0), lanes 16-31 hold sum(d1)
                if ((lane & 15) == jp) mylogit = m;
            }
            float l = mylogit + biasv + neg_log_ec((float)labv);
            acc += sigmoid_xent(l, tt);
        }
        acc += __shfl_xor_sync(0xffffffff, acc, 16);
        acc += __shfl_xor_sync(0xffffffff, acc, 8);
        acc += __shfl_xor_sync(0xffffffff, acc, 4);
        acc += __shfl_xor_sync(0xffffffff, acc, 2);
        acc += __shfl_xor_sync(0xffffffff, acc, 1);
        if (lane == 0) sm.tred[wid] = acc;
        __syncthreads();
        if (tid == 0) {
            float s = 0.0f;
#pragma unroll
            for (int i = 0; i < 8; i++) s += sm.tred[i];
            atomicAdd(out + b, s);
        }
    }
}

// ---------------- launch ---------------------------------------------------
extern "C" void kernel_launch(void* const* d_in, const int* in_sizes, int n_in,
                              void* d_out, int out_size) {
    const float* inputs  = (const float*)d_in[0];
    const float* w       = (const float*)d_in[1];
    const float* bias    = (const float*)d_in[2];
    const int*   labels  = (const int*)d_in[3];
    const int*   sampled = (const int*)d_in[4];
    float*       out     = (float*)d_out;

    const int conv_units = WG_UNITS + A_UNITS + BATCH;
    convert_kernel<<<(conv_units + 255) / 256, 256>>>(inputs, w, bias, sampled, out);
    fused_kernel<<<768, 256>>>(inputs, w, bias, labels, out);
}